// round 6
// baseline (speedup 1.0000x reference)
#include <cuda_runtime.h>
#include <math.h>

// ---------------- problem constants ----------------
#define BATCHN 4
#define SEQ    4096
#define DMODEL 1024
#define DINNER 2048
#define DSTATE 16
#define BLTOT  (BATCHN*SEQ)        // 16384 rows
#define CLEN   64                  // scan chunk length
#define NCHUNK (SEQ/CLEN)          // 64 chunks per batch

// ---------------- scratch (static device memory; no allocations) ----------------
__device__ float g_xr[BLTOT * (2*DINNER)];     // 16384 x 4096  (x_main | res)
__device__ float g_xc[BLTOT * DINNER];         // 16384 x 2048  (xc, later gated y)
__device__ float g_btct[BLTOT * 32];           // Bt (0..15) | Ct (16..31)
__device__ float g_state[BLTOT * DSTATE];      // chunk-local scan states
__device__ float g_chunkend [BATCHN*DSTATE*NCHUNK];
__device__ float g_chunkinit[BATCHN*DSTATE*NCHUNK];
__device__ float g_ys[BLTOT];

// ---------------- helpers ----------------
__device__ __forceinline__ float siluf(float v) {
    return v / (1.0f + __expf(-v));
}
__device__ __forceinline__ float softplusf(float a) {
    return (a > 20.0f) ? a : log1pf(expf(a));
}

// ---------------- double-buffered register-blocked SGEMM ----------------
// C[M,N] = A[M,K] * B[K,N], all row-major. M%128==0, N%128==0, K%16==0.
#define BM 128
#define BN 128
#define BKK 8
#define TM 8
#define TN 8

__global__ __launch_bounds__(256, 2)
void sgemm_kernel(int M, int N, int K,
                  const float* __restrict__ A,
                  const float* __restrict__ B,
                  float* __restrict__ C)
{
    __shared__ float As[2][BKK][BM];
    __shared__ float Bs[2][BKK][BN];

    const int tid = threadIdx.x;          // 256 threads
    const int brow = blockIdx.y;
    const int bcol = blockIdx.x;

    const float* Ab = A + (size_t)brow * BM * K;
    const float* Bb = B + (size_t)bcol * BN;
    float*       Cb = C + (size_t)brow * BM * N + (size_t)bcol * BN;

    // A tile loads: 128 rows x 8 k = 256 float4
    const int arow = tid >> 1;
    const int acol = (tid & 1) * 4;
    // B tile loads: 8 rows x 128 cols = 256 float4
    const int brw = tid >> 5;
    const int bcl = (tid & 31) * 4;

    const int trow = (tid >> 4) * TM;     // 16x16 thread grid of 8x8 tiles
    const int tcol = (tid & 15) * TN;

    float acc[TM][TN];
    #pragma unroll
    for (int i = 0; i < TM; i++)
        #pragma unroll
        for (int j = 0; j < TN; j++) acc[i][j] = 0.0f;

    float ra[TM], rb[TN];

    // preload tile 0 into buffer 0
    {
        float4 av = *(const float4*)(Ab + (size_t)arow * K + acol);
        As[0][acol + 0][arow] = av.x;
        As[0][acol + 1][arow] = av.y;
        As[0][acol + 2][arow] = av.z;
        As[0][acol + 3][arow] = av.w;
        float4 bv = *(const float4*)(Bb + (size_t)brw * N + bcl);
        *(float4*)&Bs[0][brw][bcl] = bv;
    }
    __syncthreads();

    int buf = 0;
    for (int k0 = 0; k0 < K; k0 += BKK) {
        const bool has_next = (k0 + BKK) < K;
        float4 av, bv;
        if (has_next) {
            av = *(const float4*)(Ab + (size_t)arow * K + (k0 + BKK) + acol);
            bv = *(const float4*)(Bb + (size_t)(k0 + BKK + brw) * N + bcl);
        }

        #pragma unroll
        for (int kk = 0; kk < BKK; kk++) {
            #pragma unroll
            for (int i = 0; i < TM; i++) ra[i] = As[buf][kk][trow + i];
            #pragma unroll
            for (int j = 0; j < TN; j++) rb[j] = Bs[buf][kk][tcol + j];
            #pragma unroll
            for (int i = 0; i < TM; i++)
                #pragma unroll
                for (int j = 0; j < TN; j++)
                    acc[i][j] = fmaf(ra[i], rb[j], acc[i][j]);
        }

        if (has_next) {
            int nb = buf ^ 1;
            As[nb][acol + 0][arow] = av.x;
            As[nb][acol + 1][arow] = av.y;
            As[nb][acol + 2][arow] = av.z;
            As[nb][acol + 3][arow] = av.w;
            *(float4*)&Bs[nb][brw][bcl] = bv;
            __syncthreads();
            buf = nb;
        }
    }

    #pragma unroll
    for (int i = 0; i < TM; i++) {
        #pragma unroll
        for (int j = 0; j < TN; j += 4) {
            float4 v = make_float4(acc[i][j], acc[i][j+1], acc[i][j+2], acc[i][j+3]);
            *(float4*)(Cb + (size_t)(trow + i) * N + tcol + j) = v;
        }
    }
}

// ---------------- depthwise conv(3) + bias + silu ----------------
__global__ void conv_silu_kernel(const float* __restrict__ conv_w,
                                 const float* __restrict__ conv_b)
{
    int idx = blockIdx.x * blockDim.x + threadIdx.x;
    if (idx >= BLTOT * DINNER) return;
    int bl = idx / DINNER;
    int i  = idx - bl * DINNER;
    int l  = bl & (SEQ - 1);

    const float* base = g_xr + (size_t)bl * (2*DINNER) + i;
    float cur  = base[0];
    float prev = (l > 0)       ? base[-(2*DINNER)] : 0.0f;
    float next = (l < SEQ - 1) ? base[ (2*DINNER)] : 0.0f;

    float w0 = __ldg(conv_w + i*3 + 0);
    float w1 = __ldg(conv_w + i*3 + 1);
    float w2 = __ldg(conv_w + i*3 + 2);

    float v = fmaf(w0, prev, fmaf(w1, cur, fmaf(w2, next, __ldg(conv_b + i))));
    g_xc[idx] = siluf(v);
}

// ---------------- Bt/Ct small GEMM: [16384,2048] @ [2048,32] ----------------
__global__ __launch_bounds__(256, 4)
void btct_kernel(const float* __restrict__ WB, const float* __restrict__ WC)
{
    __shared__ float Xs[64][33];
    __shared__ float Ws[32][32];

    const int tid = threadIdx.x;
    const int rowBase = blockIdx.x * 64;

    const int crow  = tid >> 2;          // 0..63
    const int jbase = (tid & 3) * 8;     // 0,8,16,24

    float acc[8];
    #pragma unroll
    for (int j = 0; j < 8; j++) acc[j] = 0.0f;

    for (int k0 = 0; k0 < DINNER; k0 += 32) {
        #pragma unroll
        for (int it = 0; it < 2; it++) {
            int slot = tid + 256 * it;      // 0..511
            int r  = slot >> 3;
            int kq = (slot & 7) * 4;
            float4 v = *(const float4*)(g_xc + (size_t)(rowBase + r) * DINNER + k0 + kq);
            Xs[r][kq + 0] = v.x; Xs[r][kq + 1] = v.y;
            Xs[r][kq + 2] = v.z; Xs[r][kq + 3] = v.w;
        }
        #pragma unroll
        for (int it = 0; it < 4; it++) {
            int slot = tid + 256 * it;      // 0..1023
            int k = slot >> 5;
            int j = slot & 31;
            float v = (j < 16) ? __ldg(WB + (size_t)(k0 + k) * DSTATE + j)
                               : __ldg(WC + (size_t)(k0 + k) * DSTATE + (j - 16));
            Ws[k][j] = v;
        }
        __syncthreads();

        #pragma unroll
        for (int kk = 0; kk < 32; kk++) {
            float xv = Xs[crow][kk];
            #pragma unroll
            for (int j = 0; j < 8; j++)
                acc[j] = fmaf(xv, Ws[kk][jbase + j], acc[j]);
        }
        __syncthreads();
    }

    float* out = g_btct + (size_t)(rowBase + crow) * 32 + jbase;
    #pragma unroll
    for (int j = 0; j < 8; j++) out[j] = acc[j];
}

// ---------------- scan phase 1: chunk-local scans ----------------
__global__ void scan_local_kernel(const float* __restrict__ Aparam)
{
    int tid = blockIdx.x * blockDim.x + threadIdx.x;
    if (tid >= BATCHN * DSTATE * NCHUNK) return;
    int s = tid & (DSTATE - 1);
    int c = (tid >> 4) & (NCHUNK - 1);
    int b = tid >> 10;

    float decay = expf(-softplusf(__ldg(Aparam + s)));

    int bl0 = b * SEQ + c * CLEN;
    float local = 0.0f;
    #pragma unroll 4
    for (int j = 0; j < CLEN; j++) {
        float v = g_btct[(size_t)(bl0 + j) * 32 + s];
        local = fmaf(local, decay, v);
        g_state[(size_t)(bl0 + j) * DSTATE + s] = local;
    }
    g_chunkend[(b * DSTATE + s) * NCHUNK + c] = local;
}

// ---------------- scan phase 2: cross-chunk combine ----------------
__global__ void scan_combine_kernel(const float* __restrict__ Aparam)
{
    int tid = threadIdx.x;
    if (tid >= BATCHN * DSTATE) return;
    int s = tid & (DSTATE - 1);
    int b = tid >> 4;

    float sp = softplusf(__ldg(Aparam + s));
    float dCL = expf(-sp * (float)CLEN);   // decay^CLEN

    float carry = 0.0f;
    int base = (b * DSTATE + s) * NCHUNK;
    for (int c = 0; c < NCHUNK; c++) {
        g_chunkinit[base + c] = carry;
        carry = fmaf(carry, dCL, g_chunkend[base + c]);
    }
}

// ---------------- scan phase 3: ys = sum_s(state_corrected * Ct) ----------------
__global__ void ys_kernel(const float* __restrict__ Aparam)
{
    int bl = blockIdx.x * blockDim.x + threadIdx.x;
    if (bl >= BLTOT) return;
    int b = bl / SEQ;
    int l = bl & (SEQ - 1);
    int c = l / CLEN;
    int j = l & (CLEN - 1);

    float acc = 0.0f;
    #pragma unroll
    for (int s = 0; s < DSTATE; s++) {
        float sp = softplusf(__ldg(Aparam + s));
        float init = g_chunkinit[(b * DSTATE + s) * NCHUNK + c];
        float corr = init * expf(-sp * (float)(j + 1));
        float st = g_state[(size_t)bl * DSTATE + s] + corr;
        acc = fmaf(st, g_btct[(size_t)bl * 32 + 16 + s], acc);
    }
    g_ys[bl] = acc;
}

// ---------------- gate: y = (ys + xc*D) * silu(res) ----------------
__global__ void gate_kernel(const float* __restrict__ Dparam)
{
    int idx = blockIdx.x * blockDim.x + threadIdx.x;
    if (idx >= BLTOT * DINNER) return;
    int bl = idx / DINNER;
    int i  = idx - bl * DINNER;

    float xcv = g_xc[idx];
    float rv  = g_xr[(size_t)bl * (2*DINNER) + DINNER + i];
    float y   = fmaf(xcv, __ldg(Dparam + i), g_ys[bl]) * siluf(rv);
    g_xc[idx] = y;
}

// ---------------- launch ----------------
extern "C" void kernel_launch(void* const* d_in, const int* in_sizes, int n_in,
                              void* d_out, int out_size)
{
    const float* x      = (const float*)d_in[0];   // (4,4096,1024)
    const float* W_in   = (const float*)d_in[1];   // (1024,4096)
    const float* conv_w = (const float*)d_in[2];   // (2048,1,3)
    const float* conv_b = (const float*)d_in[3];   // (2048,)
    const float* W_B    = (const float*)d_in[4];   // (2048,16)
    const float* W_C    = (const float*)d_in[5];   // (2048,16)
    const float* Aparam = (const float*)d_in[6];   // (16,)
    const float* Dparam = (const float*)d_in[7];   // (2048,)
    const float* W_out  = (const float*)d_in[8];   // (2048,1024)
    float* out = (float*)d_out;                    // (4,4096,1024)

    float* xr;  cudaGetSymbolAddress((void**)&xr,  g_xr);
    float* xc;  cudaGetSymbolAddress((void**)&xc,  g_xc);

    // 1) xr = x @ W_in   (16384 x 1024 @ 1024 x 4096)
    {
        dim3 grid((2*DINNER)/BN, BLTOT/BM);
        sgemm_kernel<<<grid, 256>>>(BLTOT, 2*DINNER, DMODEL, x, W_in, xr);
    }

    // 2) depthwise conv + silu
    {
        int total = BLTOT * DINNER;
        conv_silu_kernel<<<(total + 255)/256, 256>>>(conv_w, conv_b);
    }

    // 3) Bt/Ct
    btct_kernel<<<BLTOT/64, 256>>>(W_B, W_C);

    // 4) scan
    scan_local_kernel<<<(BATCHN*DSTATE*NCHUNK + 255)/256, 256>>>(Aparam);
    scan_combine_kernel<<<1, 64>>>(Aparam);
    ys_kernel<<<(BLTOT + 255)/256, 256>>>(Aparam);

    // 5) gate (in-place over g_xc)
    {
        int total = BLTOT * DINNER;
        gate_kernel<<<(total + 255)/256, 256>>>(Dparam);
    }

    // 6) out = y @ W_out   (16384 x 2048 @ 2048 x 1024)
    {
        dim3 grid(DMODEL/BN, BLTOT/BM);
        sgemm_kernel<<<grid, 256>>>(BLTOT, DMODEL, DINNER, xc, W_out, out);
    }
}

// round 15
// speedup vs baseline: 2.5682x; 2.5682x over previous
#include <cuda_runtime.h>
#include <math.h>
#include <stdint.h>

// ---------------- problem constants ----------------
#define BATCHN 4
#define SEQ    4096
#define DMODEL 1024
#define DINNER 2048
#define DSTATE 16
#define BLTOT  (BATCHN*SEQ)        // 16384 rows
#define CLEN   64                  // scan chunk length
#define NCHUNK (SEQ/CLEN)          // 64 chunks per batch

// ---------------- scratch (static device memory; no allocations) ----------------
__device__ float g_xr[BLTOT * (2*DINNER)];     // 16384 x 4096  (x_main | res)
__device__ float g_xc[BLTOT * DINNER];         // 16384 x 2048  (xc, later gated y)
__device__ float g_btct[BLTOT * 32];           // Bt (0..15) | Ct (16..31)
__device__ float g_state[BLTOT * DSTATE];      // chunk-local scan states
__device__ float g_chunkend [BATCHN*DSTATE*NCHUNK];
__device__ float g_chunkinit[BATCHN*DSTATE*NCHUNK];
__device__ float g_ys[BLTOT];

// ---------------- helpers ----------------
__device__ __forceinline__ float siluf(float v) {
    return v / (1.0f + __expf(-v));
}
__device__ __forceinline__ float softplusf(float a) {
    return (a > 20.0f) ? a : log1pf(expf(a));
}
__device__ __forceinline__ uint32_t f2tf32(float f) {
    uint32_t r;
    asm("cvt.rna.tf32.f32 %0, %1;" : "=r"(r) : "f"(f));
    return r;
}

// ---------------- tf32 tensor-core GEMM ----------------
// C[M,N] = A[M,K] * B[K,N], row-major. M%128==0, N%128==0, K%16==0.
// Block 128x128x16, 256 threads = 8 warps (2 over M x 4 over N),
// warp tile 64x32 = 4x4 m16n8k8 mma tiles. Double-buffered smem, tf32
// conversion at smem-store time. Padded strides (20 / 136) are
// conflict-free for the canonical quad fragment loads.
#define TBM 128
#define TBN 128
#define TBK 16
#define APAD 20
#define BPAD 136

__global__ __launch_bounds__(256)
void tf32gemm_kernel(int M, int N, int K,
                     const float* __restrict__ A,
                     const float* __restrict__ B,
                     float* __restrict__ C)
{
    __shared__ uint32_t As[2][TBM][APAD];   // [row][k]
    __shared__ uint32_t Bs[2][TBK][BPAD];   // [k][col]

    const int tid  = threadIdx.x;
    const int lane = tid & 31;
    const int wid  = tid >> 5;          // 0..7
    const int warp_m = wid & 1;         // 2 warps over M (64 rows each)
    const int warp_n = wid >> 1;        // 4 warps over N (32 cols each)
    const int group = lane >> 2;        // 0..7
    const int tig   = lane & 3;         // 0..3

    const int brow = blockIdx.y;
    const int bcol = blockIdx.x;

    const float* Ab = A + (size_t)brow * TBM * K;
    const float* Bb = B + (size_t)bcol * TBN;
    float*       Cb = C + (size_t)brow * TBM * N + (size_t)bcol * TBN;

    // A tile: 128 rows x 16 k = 512 float4; thread does rows arow, arow+64
    const int arow = tid >> 2;          // 0..63
    const int acol = (tid & 3) * 4;     // 0,4,8,12
    // B tile: 16 rows x 128 cols = 512 float4; thread does rows brw, brw+8
    const int brw = tid >> 5;           // 0..7
    const int bcl = (tid & 31) * 4;

    float acc[4][4][4];
    #pragma unroll
    for (int mt = 0; mt < 4; mt++)
        #pragma unroll
        for (int nt = 0; nt < 4; nt++)
            #pragma unroll
            for (int e = 0; e < 4; e++) acc[mt][nt][e] = 0.0f;

    // preload tile 0
    {
        #pragma unroll
        for (int h = 0; h < 2; h++) {
            int r = arow + h * 64;
            float4 av = *(const float4*)(Ab + (size_t)r * K + acol);
            As[0][r][acol + 0] = f2tf32(av.x);
            As[0][r][acol + 1] = f2tf32(av.y);
            As[0][r][acol + 2] = f2tf32(av.z);
            As[0][r][acol + 3] = f2tf32(av.w);
        }
        #pragma unroll
        for (int h = 0; h < 2; h++) {
            int r = brw + h * 8;
            float4 bv = *(const float4*)(Bb + (size_t)r * N + bcl);
            Bs[0][r][bcl + 0] = f2tf32(bv.x);
            Bs[0][r][bcl + 1] = f2tf32(bv.y);
            Bs[0][r][bcl + 2] = f2tf32(bv.z);
            Bs[0][r][bcl + 3] = f2tf32(bv.w);
        }
    }
    __syncthreads();

    const int rb_warp = warp_m * 64;
    const int cb_warp = warp_n * 32;

    int buf = 0;
    for (int k0 = 0; k0 < K; k0 += TBK) {
        const bool has_next = (k0 + TBK) < K;
        float4 av0, av1, bv0, bv1;
        if (has_next) {
            av0 = *(const float4*)(Ab + (size_t)(arow     ) * K + (k0 + TBK) + acol);
            av1 = *(const float4*)(Ab + (size_t)(arow + 64) * K + (k0 + TBK) + acol);
            bv0 = *(const float4*)(Bb + (size_t)(k0 + TBK + brw    ) * N + bcl);
            bv1 = *(const float4*)(Bb + (size_t)(k0 + TBK + brw + 8) * N + bcl);
        }

        #pragma unroll
        for (int ks = 0; ks < TBK; ks += 8) {
            uint32_t af[4][4];
            uint32_t bfr[4][2];
            #pragma unroll
            for (int mt = 0; mt < 4; mt++) {
                int rb = rb_warp + mt * 16 + group;
                af[mt][0] = As[buf][rb    ][ks + tig];
                af[mt][1] = As[buf][rb + 8][ks + tig];
                af[mt][2] = As[buf][rb    ][ks + tig + 4];
                af[mt][3] = As[buf][rb + 8][ks + tig + 4];
            }
            #pragma unroll
            for (int nt = 0; nt < 4; nt++) {
                int cb = cb_warp + nt * 8 + group;
                bfr[nt][0] = Bs[buf][ks + tig    ][cb];
                bfr[nt][1] = Bs[buf][ks + tig + 4][cb];
            }
            #pragma unroll
            for (int mt = 0; mt < 4; mt++)
                #pragma unroll
                for (int nt = 0; nt < 4; nt++) {
                    asm volatile(
                        "mma.sync.aligned.m16n8k8.row.col.f32.tf32.tf32.f32 "
                        "{%0,%1,%2,%3}, {%4,%5,%6,%7}, {%8,%9}, {%0,%1,%2,%3};"
                        : "+f"(acc[mt][nt][0]), "+f"(acc[mt][nt][1]),
                          "+f"(acc[mt][nt][2]), "+f"(acc[mt][nt][3])
                        : "r"(af[mt][0]), "r"(af[mt][1]),
                          "r"(af[mt][2]), "r"(af[mt][3]),
                          "r"(bfr[nt][0]), "r"(bfr[nt][1]));
                }
        }

        if (has_next) {
            int nb = buf ^ 1;
            As[nb][arow     ][acol + 0] = f2tf32(av0.x);
            As[nb][arow     ][acol + 1] = f2tf32(av0.y);
            As[nb][arow     ][acol + 2] = f2tf32(av0.z);
            As[nb][arow     ][acol + 3] = f2tf32(av0.w);
            As[nb][arow + 64][acol + 0] = f2tf32(av1.x);
            As[nb][arow + 64][acol + 1] = f2tf32(av1.y);
            As[nb][arow + 64][acol + 2] = f2tf32(av1.z);
            As[nb][arow + 64][acol + 3] = f2tf32(av1.w);
            Bs[nb][brw    ][bcl + 0] = f2tf32(bv0.x);
            Bs[nb][brw    ][bcl + 1] = f2tf32(bv0.y);
            Bs[nb][brw    ][bcl + 2] = f2tf32(bv0.z);
            Bs[nb][brw    ][bcl + 3] = f2tf32(bv0.w);
            Bs[nb][brw + 8][bcl + 0] = f2tf32(bv1.x);
            Bs[nb][brw + 8][bcl + 1] = f2tf32(bv1.y);
            Bs[nb][brw + 8][bcl + 2] = f2tf32(bv1.z);
            Bs[nb][brw + 8][bcl + 3] = f2tf32(bv1.w);
            __syncthreads();
            buf = nb;
        }
    }

    // epilogue: c0,c1 -> (row rb+group, col cb+2*tig); c2,c3 -> row+8
    #pragma unroll
    for (int mt = 0; mt < 4; mt++) {
        int r0 = rb_warp + mt * 16 + group;
        #pragma unroll
        for (int nt = 0; nt < 4; nt++) {
            int c0 = cb_warp + nt * 8 + tig * 2;
            float2 lo = make_float2(acc[mt][nt][0], acc[mt][nt][1]);
            float2 hi = make_float2(acc[mt][nt][2], acc[mt][nt][3]);
            *(float2*)(Cb + (size_t)r0 * N + c0)       = lo;
            *(float2*)(Cb + (size_t)(r0 + 8) * N + c0) = hi;
        }
    }
}

// ---------------- depthwise conv(3) + bias + silu ----------------
__global__ void conv_silu_kernel(const float* __restrict__ conv_w,
                                 const float* __restrict__ conv_b)
{
    int idx = blockIdx.x * blockDim.x + threadIdx.x;
    if (idx >= BLTOT * DINNER) return;
    int bl = idx / DINNER;
    int i  = idx - bl * DINNER;
    int l  = bl & (SEQ - 1);

    const float* base = g_xr + (size_t)bl * (2*DINNER) + i;
    float cur  = base[0];
    float prev = (l > 0)       ? base[-(2*DINNER)] : 0.0f;
    float next = (l < SEQ - 1) ? base[ (2*DINNER)] : 0.0f;

    float w0 = __ldg(conv_w + i*3 + 0);
    float w1 = __ldg(conv_w + i*3 + 1);
    float w2 = __ldg(conv_w + i*3 + 2);

    float v = fmaf(w0, prev, fmaf(w1, cur, fmaf(w2, next, __ldg(conv_b + i))));
    g_xc[idx] = siluf(v);
}

// ---------------- Bt/Ct small GEMM: [16384,2048] @ [2048,32] ----------------
__global__ __launch_bounds__(256, 4)
void btct_kernel(const float* __restrict__ WB, const float* __restrict__ WC)
{
    __shared__ float Xs[64][33];
    __shared__ float Ws[32][32];

    const int tid = threadIdx.x;
    const int rowBase = blockIdx.x * 64;

    const int crow  = tid >> 2;          // 0..63
    const int jbase = (tid & 3) * 8;     // 0,8,16,24

    float acc[8];
    #pragma unroll
    for (int j = 0; j < 8; j++) acc[j] = 0.0f;

    for (int k0 = 0; k0 < DINNER; k0 += 32) {
        #pragma unroll
        for (int it = 0; it < 2; it++) {
            int slot = tid + 256 * it;      // 0..511
            int r  = slot >> 3;
            int kq = (slot & 7) * 4;
            float4 v = *(const float4*)(g_xc + (size_t)(rowBase + r) * DINNER + k0 + kq);
            Xs[r][kq + 0] = v.x; Xs[r][kq + 1] = v.y;
            Xs[r][kq + 2] = v.z; Xs[r][kq + 3] = v.w;
        }
        #pragma unroll
        for (int it = 0; it < 4; it++) {
            int slot = tid + 256 * it;      // 0..1023
            int k = slot >> 5;
            int j = slot & 31;
            float v = (j < 16) ? __ldg(WB + (size_t)(k0 + k) * DSTATE + j)
                               : __ldg(WC + (size_t)(k0 + k) * DSTATE + (j - 16));
            Ws[k][j] = v;
        }
        __syncthreads();

        #pragma unroll
        for (int kk = 0; kk < 32; kk++) {
            float xv = Xs[crow][kk];
            #pragma unroll
            for (int j = 0; j < 8; j++)
                acc[j] = fmaf(xv, Ws[kk][jbase + j], acc[j]);
        }
        __syncthreads();
    }

    float* out = g_btct + (size_t)(rowBase + crow) * 32 + jbase;
    #pragma unroll
    for (int j = 0; j < 8; j++) out[j] = acc[j];
}

// ---------------- scan phase 1: chunk-local scans ----------------
__global__ void scan_local_kernel(const float* __restrict__ Aparam)
{
    int tid = blockIdx.x * blockDim.x + threadIdx.x;
    if (tid >= BATCHN * DSTATE * NCHUNK) return;
    int s = tid & (DSTATE - 1);
    int c = (tid >> 4) & (NCHUNK - 1);
    int b = tid >> 10;

    float decay = expf(-softplusf(__ldg(Aparam + s)));

    int bl0 = b * SEQ + c * CLEN;
    float local = 0.0f;
    #pragma unroll 4
    for (int j = 0; j < CLEN; j++) {
        float v = g_btct[(size_t)(bl0 + j) * 32 + s];
        local = fmaf(local, decay, v);
        g_state[(size_t)(bl0 + j) * DSTATE + s] = local;
    }
    g_chunkend[(b * DSTATE + s) * NCHUNK + c] = local;
}

// ---------------- scan phase 2: cross-chunk combine ----------------
__global__ void scan_combine_kernel(const float* __restrict__ Aparam)
{
    int tid = threadIdx.x;
    if (tid >= BATCHN * DSTATE) return;
    int s = tid & (DSTATE - 1);
    int b = tid >> 4;

    float sp = softplusf(__ldg(Aparam + s));
    float dCL = expf(-sp * (float)CLEN);   // decay^CLEN

    float carry = 0.0f;
    int base = (b * DSTATE + s) * NCHUNK;
    for (int c = 0; c < NCHUNK; c++) {
        g_chunkinit[base + c] = carry;
        carry = fmaf(carry, dCL, g_chunkend[base + c]);
    }
}

// ---------------- scan phase 3: ys = sum_s(state_corrected * Ct) ----------------
__global__ void ys_kernel(const float* __restrict__ Aparam)
{
    int bl = blockIdx.x * blockDim.x + threadIdx.x;
    if (bl >= BLTOT) return;
    int b = bl / SEQ;
    int l = bl & (SEQ - 1);
    int c = l / CLEN;
    int j = l & (CLEN - 1);

    float acc = 0.0f;
    #pragma unroll
    for (int s = 0; s < DSTATE; s++) {
        float sp = softplusf(__ldg(Aparam + s));
        float init = g_chunkinit[(b * DSTATE + s) * NCHUNK + c];
        float corr = init * expf(-sp * (float)(j + 1));
        float st = g_state[(size_t)bl * DSTATE + s] + corr;
        acc = fmaf(st, g_btct[(size_t)bl * 32 + 16 + s], acc);
    }
    g_ys[bl] = acc;
}

// ---------------- gate: y = (ys + xc*D) * silu(res) ----------------
__global__ void gate_kernel(const float* __restrict__ Dparam)
{
    int idx = blockIdx.x * blockDim.x + threadIdx.x;
    if (idx >= BLTOT * DINNER) return;
    int bl = idx / DINNER;
    int i  = idx - bl * DINNER;

    float xcv = g_xc[idx];
    float rv  = g_xr[(size_t)bl * (2*DINNER) + DINNER + i];
    float y   = fmaf(xcv, __ldg(Dparam + i), g_ys[bl]) * siluf(rv);
    g_xc[idx] = y;
}

// ---------------- launch ----------------
extern "C" void kernel_launch(void* const* d_in, const int* in_sizes, int n_in,
                              void* d_out, int out_size)
{
    const float* x      = (const float*)d_in[0];   // (4,4096,1024)
    const float* W_in   = (const float*)d_in[1];   // (1024,4096)
    const float* conv_w = (const float*)d_in[2];   // (2048,1,3)
    const float* conv_b = (const float*)d_in[3];   // (2048,)
    const float* W_B    = (const float*)d_in[4];   // (2048,16)
    const float* W_C    = (const float*)d_in[5];   // (2048,16)
    const float* Aparam = (const float*)d_in[6];   // (16,)
    const float* Dparam = (const float*)d_in[7];   // (2048,)
    const float* W_out  = (const float*)d_in[8];   // (2048,1024)
    float* out = (float*)d_out;                    // (4,4096,1024)

    float* xr;  cudaGetSymbolAddress((void**)&xr,  g_xr);
    float* xc;  cudaGetSymbolAddress((void**)&xc,  g_xc);

    // 1) xr = x @ W_in   (16384 x 1024 @ 1024 x 4096)
    {
        dim3 grid((2*DINNER)/TBN, BLTOT/TBM);
        tf32gemm_kernel<<<grid, 256>>>(BLTOT, 2*DINNER, DMODEL, x, W_in, xr);
    }

    // 2) depthwise conv + silu
    {
        int total = BLTOT * DINNER;
        conv_silu_kernel<<<(total + 255)/256, 256>>>(conv_w, conv_b);
    }

    // 3) Bt/Ct
    btct_kernel<<<BLTOT/64, 256>>>(W_B, W_C);

    // 4) scan
    scan_local_kernel<<<(BATCHN*DSTATE*NCHUNK + 255)/256, 256>>>(Aparam);
    scan_combine_kernel<<<1, 64>>>(Aparam);
    ys_kernel<<<(BLTOT + 255)/256, 256>>>(Aparam);

    // 5) gate (in-place over g_xc)
    {
        int total = BLTOT * DINNER;
        gate_kernel<<<(total + 255)/256, 256>>>(Dparam);
    }

    // 6) out = y @ W_out   (16384 x 2048 @ 2048 x 1024)
    {
        dim3 grid(DMODEL/TBN, BLTOT/TBM);
        tf32gemm_kernel<<<grid, 256>>>(BLTOT, DMODEL, DINNER, xc, W_out, out);
    }
}